// round 16
// baseline (speedup 1.0000x reference)
#include <cuda_runtime.h>
#include <cuda_bf16.h>
#include <cstdint>

// Problem constants (fixed by the dataset)
#define N_NODES  50000
#define N_EDGES  800000
#define IN_C     768
#define HID      256
#define OUT_C    128
#define N_GRAPHS 256
#define F_TOT    384
#define F4_TOT   96

// ---------------------------------------------------------------------------
// Scratch (device globals)
// ---------------------------------------------------------------------------
__device__ float g_h   [N_NODES * HID];     // GEMM output (pre-agg), reused both layers
__device__ float g_deg [N_NODES];
__device__ float g_dinv[N_NODES];
__device__ float g_pool[N_GRAPHS * F_TOT];
__device__ float g_cnt [N_GRAPHS];
__device__ int   g_idx64;

// CSR
__device__ int   g_off   [N_NODES + 1];
__device__ int   g_cursor[N_NODES];
__device__ int   g_csr   [N_EDGES];
__device__ float g_csrw  [N_EDGES];

// bf16 split A for layer-2 GEMM (filled by agg1 epilogue)
__device__ __nv_bfloat16 g_Ah[N_NODES * HID];
__device__ __nv_bfloat16 g_Al[N_NODES * HID];
// bf16 split weights [N][K]
__device__ __nv_bfloat16 g_B1h[HID * IN_C];
__device__ __nv_bfloat16 g_B1l[HID * IN_C];
__device__ __nv_bfloat16 g_B2h[OUT_C * HID];
__device__ __nv_bfloat16 g_B2l[OUT_C * HID];

// ---------------------------------------------------------------------------
// Helpers
// ---------------------------------------------------------------------------
__device__ __forceinline__ uint32_t smem_to_u32(const void* p) {
    uint32_t a;
    asm("{ .reg .u64 t; cvta.to.shared.u64 t, %1; cvt.u32.u64 %0, t; }"
        : "=r"(a) : "l"(p));
    return a;
}
__device__ __forceinline__ void ldsm_x4(uint32_t* r, uint32_t addr) {
    asm volatile("ldmatrix.sync.aligned.m8n8.x4.shared.b16 {%0,%1,%2,%3}, [%4];"
                 : "=r"(r[0]), "=r"(r[1]), "=r"(r[2]), "=r"(r[3]) : "r"(addr));
}
__device__ __forceinline__ void ldsm_x2(uint32_t* r, uint32_t addr) {
    asm volatile("ldmatrix.sync.aligned.m8n8.x2.shared.b16 {%0,%1}, [%2];"
                 : "=r"(r[0]), "=r"(r[1]) : "r"(addr));
}
__device__ __forceinline__ void mma_bf16(float* d, const uint32_t* a, const uint32_t* b) {
    asm volatile("mma.sync.aligned.m16n8k16.row.col.f32.bf16.bf16.f32 "
                 "{%0,%1,%2,%3}, {%4,%5,%6,%7}, {%8,%9}, {%0,%1,%2,%3};"
                 : "+f"(d[0]), "+f"(d[1]), "+f"(d[2]), "+f"(d[3])
                 : "r"(a[0]), "r"(a[1]), "r"(a[2]), "r"(a[3]),
                   "r"(b[0]), "r"(b[1]));
}
__device__ __forceinline__ void cp16(uint32_t dst, const void* src, int bytes) {
    asm volatile("cp.async.ca.shared.global [%0], [%1], 16, %2;"
                 :: "r"(dst), "l"(src), "r"(bytes) : "memory");
}
#define CP_COMMIT() asm volatile("cp.async.commit_group;" ::: "memory")
template <int NG> __device__ __forceinline__ void cp_wait() {
    asm volatile("cp.async.wait_group %0;" :: "n"(NG) : "memory");
}

// Scalar bf16 split
__device__ __forceinline__ void bf16_split(float x, unsigned short& hi, unsigned short& lo) {
    __nv_bfloat16 h = __float2bfloat16(x);
    float r = x - __bfloat162float(h);
    __nv_bfloat16 l = __float2bfloat16(r);
    hi = __bfloat16_as_ushort(h);
    lo = __bfloat16_as_ushort(l);
}

// Packed float4 -> (hi bf16x4, lo bf16x4) split via cvt.rn.bf16x2.f32.
__device__ __forceinline__ void split_f4(float4 v, uint2& hw, uint2& lw) {
    uint32_t h01, h23;
    asm("cvt.rn.bf16x2.f32 %0, %1, %2;" : "=r"(h01) : "f"(v.y), "f"(v.x));
    asm("cvt.rn.bf16x2.f32 %0, %1, %2;" : "=r"(h23) : "f"(v.w), "f"(v.z));
    float r0 = v.x - __uint_as_float(h01 << 16);
    float r1 = v.y - __uint_as_float(h01 & 0xFFFF0000u);
    float r2 = v.z - __uint_as_float(h23 << 16);
    float r3 = v.w - __uint_as_float(h23 & 0xFFFF0000u);
    uint32_t l01, l23;
    asm("cvt.rn.bf16x2.f32 %0, %1, %2;" : "=r"(l01) : "f"(r1), "f"(r0));
    asm("cvt.rn.bf16x2.f32 %0, %1, %2;" : "=r"(l23) : "f"(r3), "f"(r2));
    hw = make_uint2(h01, h23);
    lw = make_uint2(l01, l23);
}

__device__ __forceinline__ int load_idx(const void* p, long long i) {
    if (g_idx64) return (int)((const long long*)p)[i];
    return ((const int*)p)[i];
}
__device__ __forceinline__ void red_add_v4(float* p, float x, float y, float z, float w) {
    asm volatile("red.global.add.v4.f32 [%0], {%1,%2,%3,%4};"
                 :: "l"(p), "f"(x), "f"(y), "f"(z), "f"(w) : "memory");
}

// ---------------------------------------------------------------------------
// Prolog kernels
// ---------------------------------------------------------------------------
__global__ void k_detect(const void* ei) {
    if (threadIdx.x == 0 && blockIdx.x == 0) {
        const long long* p = (const long long*)ei;
        int ok = 1;
        for (int i = 0; i < 256; i++) {
            long long v = p[i];
            if (v < 0 || v >= N_NODES) { ok = 0; break; }
        }
        g_idx64 = ok;
    }
}

__global__ void k_zero() {
    int i = blockIdx.x * blockDim.x + threadIdx.x;
    if (i < N_NODES) g_deg[i] = 0.f;
    if (i < N_GRAPHS * F_TOT) g_pool[i] = 0.f;
    if (i < N_GRAPHS) g_cnt[i] = 0.f;
}

// Tiled-transpose weight split: W[K][N] fp32 -> Bh/Bl[N][K] bf16.
// 32x32 tile via smem; coalesced loads AND stores (the naive version's
// 2-byte scattered stores were ~5x slower than byte count warrants).
template <int K, int N>
__global__ void __launch_bounds__(256)
k_splitW_t(const float* __restrict__ W,
           __nv_bfloat16* __restrict__ Bh, __nv_bfloat16* __restrict__ Bl) {
    __shared__ unsigned short sh[32][33];
    __shared__ unsigned short sl[32][33];
    const int k0 = blockIdx.x * 32;
    const int n0 = blockIdx.y * 32;
    const int tx = threadIdx.x & 31;
    const int ty = threadIdx.x >> 5;          // 0..7
#pragma unroll
    for (int i = 0; i < 4; i++) {
        int k = ty * 4 + i;                   // 0..31
        float v = W[(size_t)(k0 + k) * N + n0 + tx];
        unsigned short hi, lo;
        bf16_split(v, hi, lo);
        sh[k][tx] = hi;
        sl[k][tx] = lo;
    }
    __syncthreads();
#pragma unroll
    for (int i = 0; i < 4; i++) {
        int n = ty * 4 + i;
        Bh[(size_t)(n0 + n) * K + k0 + tx] = __ushort_as_bfloat16(sh[tx][n]);
        Bl[(size_t)(n0 + n) * K + k0 + tx] = __ushort_as_bfloat16(sl[tx][n]);
    }
}

__global__ void k_deg(const void* __restrict__ ei) {
    int e = blockIdx.x * blockDim.x + threadIdx.x;
    if (e < N_EDGES) {
        int d = load_idx(ei, (long long)N_EDGES + e);
        atomicAdd(&g_deg[d], 1.0f);
    }
}
__global__ void k_dinv() {
    int i = blockIdx.x * blockDim.x + threadIdx.x;
    if (i < N_NODES) g_dinv[i] = rsqrtf(g_deg[i] + 1.0f);
}
__global__ void k_cnt(const void* __restrict__ batch) {
    int i = blockIdx.x * blockDim.x + threadIdx.x;
    if (i < N_NODES) {
        int g = load_idx(batch, i);
        atomicAdd(&g_cnt[g], 1.0f);
    }
}

// Exclusive scan of deg -> g_off / g_cursor. Single block, 1024 threads.
__global__ void k_scan() {
    __shared__ int swarp[32];
    __shared__ int s_carry;
    int tid = threadIdx.x, lane = tid & 31, wid = tid >> 5;
    if (tid == 0) s_carry = 0;
    __syncthreads();
    for (int base = 0; base < N_NODES; base += 1024) {
        int i = base + tid;
        int v = (i < N_NODES) ? (int)g_deg[i] : 0;
        int incl = v;
#pragma unroll
        for (int o = 1; o < 32; o <<= 1) {
            int t = __shfl_up_sync(0xFFFFFFFFu, incl, o);
            if (lane >= o) incl += t;
        }
        if (lane == 31) swarp[wid] = incl;
        __syncthreads();
        if (wid == 0) {
            int ws = swarp[lane];
            int wincl = ws;
#pragma unroll
            for (int o = 1; o < 32; o <<= 1) {
                int t = __shfl_up_sync(0xFFFFFFFFu, wincl, o);
                if (lane >= o) wincl += t;
            }
            swarp[lane] = wincl - ws;
        }
        __syncthreads();
        int ex = s_carry + swarp[wid] + incl - v;
        if (i < N_NODES) { g_off[i] = ex; g_cursor[i] = ex; }
        __syncthreads();
        if (tid == 1023) s_carry = ex + v;
        __syncthreads();
    }
    if (threadIdx.x == 0) g_off[N_NODES] = s_carry;
}

__global__ void k_fill(const void* __restrict__ ei) {
    int e = blockIdx.x * blockDim.x + threadIdx.x;
    if (e >= N_EDGES) return;
    int s = load_idx(ei, e);
    int d = load_idx(ei, (long long)N_EDGES + e);
    int p = atomicAdd(&g_cursor[d], 1);
    g_csr[p]  = s;
    g_csrw[p] = g_dinv[s] * g_dinv[d];
}

// ---------------------------------------------------------------------------
// Pipelined bf16-split GEMM (round-15 proven).
//   AFP32=true : A fp32 [M,K]; double-buffered A32, single Astage, double
//                Bstage (92 KB -> 2 CTAs/SM); prefetch-first pipeline.
//   AFP32=false: A pre-split bf16 hi/lo arrays (double-buffered, 80 KB).
// ---------------------------------------------------------------------------
#define PITCH    80
#define TILE_B   (128 * PITCH)        // 10240
#define STAGE_B  (4 * TILE_B)         // 40960 (AFP32=false stage)
#define A32_B    16384                // 128 x 32 fp32
#define SMEM_T   (2 * A32_B + 2 * TILE_B + 4 * TILE_B)   // 94208 (AFP32=true)

template <bool AFP32>
__global__ void __launch_bounds__(256, 2)
k_gemm(const float* __restrict__ A32,
       const __nv_bfloat16* __restrict__ Ah, const __nv_bfloat16* __restrict__ Al,
       const __nv_bfloat16* __restrict__ Bh, const __nv_bfloat16* __restrict__ Bl,
       float* __restrict__ C, int M, int Nld, int K) {
    extern __shared__ char smem[];
    const int tid  = threadIdx.x;
    const int lane = tid & 31;
    const int wid  = tid >> 5;
    const int wm   = (wid & 1) * 64;
    const int wn   = (wid >> 1) * 32;
    const int mBase = blockIdx.y * 128;
    const int nBase = blockIdx.x * 128;
    const uint32_t sbase = smem_to_u32(smem);
    const uint32_t sAstage = sbase + 2 * A32_B;
    const uint32_t sBstage = sAstage + 2 * TILE_B;

    float acc[4][4][4];
#pragma unroll
    for (int i = 0; i < 4; i++)
#pragma unroll
        for (int j = 0; j < 4; j++)
#pragma unroll
            for (int q = 0; q < 4; q++) acc[i][j][q] = 0.f;

    const int aRow = lane & 15;
    const int aK   = (lane >> 4) * 16;
    const int bRow = lane & 7;
    const int bK   = ((lane & 15) >> 3) * 16;

    const int nch = K >> 5;

    auto stage = [&](int ch, int buf) {
        const int k0 = ch << 5;
        if (AFP32) {
            const uint32_t sa = sbase + buf * A32_B;
#pragma unroll
            for (int t = 0; t < 4; t++) {
                int idx = t * 256 + tid;          // 0..1023
                int m = idx >> 3, q = idx & 7;
                int gm = mBase + m;
                int ok = (gm < M) ? 16 : 0;
                if (!ok) gm = 0;
                cp16(sa + m * 128 + q * 16, A32 + (size_t)gm * K + k0 + q * 4, ok);
            }
            const uint32_t sbB = sBstage + buf * (2 * TILE_B);
#pragma unroll
            for (int t = 0; t < 2; t++) {
                int idx = t * 256 + tid;          // 0..511
                int n = idx >> 2, q = idx & 3;
                uint32_t so = sbB + n * PITCH + q * 16;
                const size_t gb = (size_t)(nBase + n) * K + k0 + q * 8;
                cp16(so,          Bh + gb, 16);
                cp16(so + TILE_B, Bl + gb, 16);
            }
        } else {
            const uint32_t sb = sbase + buf * STAGE_B;
#pragma unroll
            for (int t = 0; t < 2; t++) {
                int idx = t * 256 + tid;          // 0..511
                int m = idx >> 2, q = idx & 3;
                uint32_t so = sb + m * PITCH + q * 16;
                int gm = mBase + m;
                int okA = (gm < M) ? 16 : 0;
                if (!okA) gm = 0;
                const size_t ga = (size_t)gm * K + k0 + q * 8;
                cp16(so,              Ah + ga, okA);
                cp16(so + TILE_B,     Al + ga, okA);
                const size_t gb = (size_t)(nBase + m) * K + k0 + q * 8;
                cp16(so + 2 * TILE_B, Bh + gb, 16);
                cp16(so + 3 * TILE_B, Bl + gb, 16);
            }
        }
    };

    stage(0, 0); CP_COMMIT();
    for (int ch = 0; ch < nch; ch++) {
        const int buf = ch & 1;

        if (ch + 1 < nch) { stage(ch + 1, buf ^ 1); CP_COMMIT(); cp_wait<1>(); }
        else              { cp_wait<0>(); }
        __syncthreads();

        if (AFP32) {
            // split A32[buf] -> Astage (single-buffered; protected by loop-end sync)
#pragma unroll
            for (int t = 0; t < 4; t++) {
                int idx = t * 256 + tid;          // 0..1023 float4s
                int m = idx >> 3, q = idx & 7;
                float4 v = *(const float4*)(smem + buf * A32_B + m * 128 + q * 16);
                uint2 hw, lw;
                split_f4(v, hw, lw);
                char* so = smem + 2 * A32_B + m * PITCH + q * 8;
                *(uint2*)(so)          = hw;
                *(uint2*)(so + TILE_B) = lw;
            }
            __syncthreads();
        }

        const uint32_t aBase = AFP32 ? sAstage : (sbase + buf * STAGE_B);
        const uint32_t bBase = AFP32 ? (sBstage + buf * (2 * TILE_B))
                                     : (aBase + 2 * TILE_B);

#pragma unroll
        for (int ks = 0; ks < 2; ks++) {
            const int koff = ks * 32;
            uint32_t bhf[4][2], blf[4][2];
#pragma unroll
            for (int nf = 0; nf < 4; nf++) {
                uint32_t ro = bBase + (uint32_t)(wn + nf * 8 + bRow) * PITCH + koff + bK;
                ldsm_x2(bhf[nf], ro);
                ldsm_x2(blf[nf], ro + TILE_B);
            }
#pragma unroll
            for (int mf = 0; mf < 4; mf++) {
                uint32_t ah[4], al[4];
                uint32_t ro = aBase + (uint32_t)(wm + mf * 16 + aRow) * PITCH + koff + aK;
                ldsm_x4(ah, ro);
                ldsm_x4(al, ro + TILE_B);
#pragma unroll
                for (int nf = 0; nf < 4; nf++) {
                    mma_bf16(acc[mf][nf], ah, bhf[nf]);
                    mma_bf16(acc[mf][nf], ah, blf[nf]);
                    mma_bf16(acc[mf][nf], al, bhf[nf]);
                }
            }
        }
        __syncthreads();
    }

#pragma unroll
    for (int mf = 0; mf < 4; mf++) {
        int r0 = mBase + wm + mf * 16 + (lane >> 2);
#pragma unroll
        for (int nf = 0; nf < 4; nf++) {
            int c0 = nBase + wn + nf * 8 + (lane & 3) * 2;
            if (r0 < M)
                *(float2*)(C + (size_t)r0 * Nld + c0) =
                    make_float2(acc[mf][nf][0], acc[mf][nf][1]);
            if (r0 + 8 < M)
                *(float2*)(C + (size_t)(r0 + 8) * Nld + c0) =
                    make_float2(acc[mf][nf][2], acc[mf][nf][3]);
        }
    }
}

// ---------------------------------------------------------------------------
// Fused CSR aggregation (warp per node, round-9 loop): selfloop + gather +
// relu + bias + node_embed + pool red + optional bf16 split for next GEMM.
// ---------------------------------------------------------------------------
template <int SH, int COFF, bool SPLIT_OUT>
__global__ void __launch_bounds__(256)
k_agg(const float* __restrict__ h, const float* __restrict__ bias,
      const void* __restrict__ batch, float* __restrict__ out_node) {
    const int gw   = (blockIdx.x * blockDim.x + threadIdx.x) >> 5;
    const int lane = threadIdx.x & 31;
    if (gw >= N_NODES) return;
    const int i = gw;
    constexpr int C = 1 << (SH - 5);
    const float4* h4 = (const float4*)h;

    float4 acc[C];
    const float di = g_dinv[i];
    const float s2 = di * di;
#pragma unroll
    for (int c = 0; c < C; c++) {
        float4 v = h4[((size_t)i << SH) + lane + c * 32];
        acc[c] = make_float4(v.x * s2, v.y * s2, v.z * s2, v.w * s2);
    }

    int j  = g_off[i];
    const int je = g_off[i + 1];
    for (; j + 1 < je; j += 2) {
        int   s0 = g_csr[j],     s1 = g_csr[j + 1];
        float w0 = g_csrw[j],    w1 = g_csrw[j + 1];
        float4 v0[C], v1[C];
#pragma unroll
        for (int c = 0; c < C; c++) {
            v0[c] = h4[((size_t)s0 << SH) + lane + c * 32];
            v1[c] = h4[((size_t)s1 << SH) + lane + c * 32];
        }
#pragma unroll
        for (int c = 0; c < C; c++) {
            acc[c].x += v0[c].x * w0 + v1[c].x * w1;
            acc[c].y += v0[c].y * w0 + v1[c].y * w1;
            acc[c].z += v0[c].z * w0 + v1[c].z * w1;
            acc[c].w += v0[c].w * w0 + v1[c].w * w1;
        }
    }
    if (j < je) {
        int   s0 = g_csr[j];
        float w0 = g_csrw[j];
#pragma unroll
        for (int c = 0; c < C; c++) {
            float4 v = h4[((size_t)s0 << SH) + lane + c * 32];
            acc[c].x += v.x * w0; acc[c].y += v.y * w0;
            acc[c].z += v.z * w0; acc[c].w += v.w * w0;
        }
    }

    const int g = load_idx(batch, i);
    const float4* bias4 = (const float4*)bias;
#pragma unroll
    for (int c = 0; c < C; c++) {
        float4 bb = bias4[lane + c * 32];
        float4 a;
        a.x = fmaxf(acc[c].x + bb.x, 0.f);
        a.y = fmaxf(acc[c].y + bb.y, 0.f);
        a.z = fmaxf(acc[c].z + bb.z, 0.f);
        a.w = fmaxf(acc[c].w + bb.w, 0.f);
        ((float4*)out_node)[(size_t)i * F4_TOT + COFF + lane + c * 32] = a;
        red_add_v4(g_pool + (((size_t)g * F4_TOT + COFF + lane + c * 32) << 2),
                   a.x, a.y, a.z, a.w);
        if (SPLIT_OUT) {
            uint2 hw, lw;
            split_f4(a, hw, lw);
            size_t o = ((size_t)i << SH) + lane + c * 32;
            ((uint2*)g_Ah)[o] = hw;
            ((uint2*)g_Al)[o] = lw;
        }
    }
}

__global__ void k_pooldiv(float* __restrict__ out_graph) {
    int tid = blockIdx.x * blockDim.x + threadIdx.x;
    if (tid >= N_GRAPHS * F4_TOT) return;
    int g = tid / F4_TOT;
    float inv = 1.0f / fmaxf(g_cnt[g], 1.0f);
    float4 v = ((float4*)g_pool)[tid];
    v.x *= inv; v.y *= inv; v.z *= inv; v.w *= inv;
    ((float4*)out_graph)[tid] = v;
}

// ---------------------------------------------------------------------------
// Launch -- round-15 schedule with the serial prolog minimized:
//   side: zero + CSR chain + W2 split (all off the critical path)
//   main: W1 split (tiled, coalesced) -> GEMM1 -> join -> agg1 -> GEMM2 ->
//         agg2 -> pooldiv
// ---------------------------------------------------------------------------
extern "C" void kernel_launch(void* const* d_in, const int* in_sizes, int n_in,
                              void* d_out, int out_size) {
    const float* x     = (const float*)d_in[0];
    const void*  ei    = d_in[1];
    const void*  batch = d_in[2];
    const float *W1, *b1, *W2, *b2;
    if (n_in >= 8) {
        W1 = (const float*)d_in[4]; b1 = (const float*)d_in[5];
        W2 = (const float*)d_in[6]; b2 = (const float*)d_in[7];
    } else {
        W1 = (const float*)d_in[3]; b1 = (const float*)d_in[4];
        W2 = (const float*)d_in[5]; b2 = (const float*)d_in[6];
    }
    float* out       = (float*)d_out;
    float* out_graph = out;
    float* out_node  = out + (size_t)N_GRAPHS * F_TOT;

    void *p_h, *p_Ah, *p_Al, *p_B1h, *p_B1l, *p_B2h, *p_B2l;
    cudaGetSymbolAddress(&p_h,   g_h);
    cudaGetSymbolAddress(&p_Ah,  g_Ah);
    cudaGetSymbolAddress(&p_Al,  g_Al);
    cudaGetSymbolAddress(&p_B1h, g_B1h);
    cudaGetSymbolAddress(&p_B1l, g_B1l);
    cudaGetSymbolAddress(&p_B2h, g_B2h);
    cudaGetSymbolAddress(&p_B2l, g_B2l);
    float* h = (float*)p_h;

    cudaFuncSetAttribute(k_gemm<true>,  cudaFuncAttributeMaxDynamicSharedMemorySize,
                         SMEM_T);
    cudaFuncSetAttribute(k_gemm<false>, cudaFuncAttributeMaxDynamicSharedMemorySize,
                         2 * STAGE_B);

    // Side stream + events (created once; first call is the non-captured
    // correctness run, so creation never happens inside capture).
    static cudaStream_t s_side = nullptr;
    static cudaEvent_t  s_fork = nullptr, s_join = nullptr;
    if (!s_side) {
        cudaStreamCreateWithFlags(&s_side, cudaStreamNonBlocking);
        cudaEventCreateWithFlags(&s_fork, cudaEventDisableTiming);
        cudaEventCreateWithFlags(&s_join, cudaEventDisableTiming);
    }

    const int T = 256;

    // ---- fork immediately: zero + CSR chain + W2 split on side ----
    cudaEventRecord(s_fork, 0);
    cudaStreamWaitEvent(s_side, s_fork, 0);
    k_zero<<<(N_GRAPHS * F_TOT + T - 1) / T, T, 0, s_side>>>();
    k_detect<<<1, 32, 0, s_side>>>(ei);
    k_deg<<<(N_EDGES + T - 1) / T, T, 0, s_side>>>(ei);
    k_dinv<<<(N_NODES + T - 1) / T, T, 0, s_side>>>();
    k_cnt<<<(N_NODES + T - 1) / T, T, 0, s_side>>>(batch);
    k_scan<<<1, 1024, 0, s_side>>>();
    k_fill<<<(N_EDGES + T - 1) / T, T, 0, s_side>>>(ei);
    k_splitW_t<HID, OUT_C><<<dim3(HID / 32, OUT_C / 32), 256, 0, s_side>>>(
        W2, (__nv_bfloat16*)p_B2h, (__nv_bfloat16*)p_B2l);
    cudaEventRecord(s_join, s_side);

    // ---- main: W1 split (tiled) -> GEMM1 ----
    k_splitW_t<IN_C, HID><<<dim3(IN_C / 32, HID / 32), 256>>>(
        W1, (__nv_bfloat16*)p_B1h, (__nv_bfloat16*)p_B1l);
    k_gemm<true><<<dim3(HID / 128, (N_NODES + 127) / 128), 256, SMEM_T>>>(
        x, nullptr, nullptr,
        (const __nv_bfloat16*)p_B1h, (const __nv_bfloat16*)p_B1l,
        h, N_NODES, HID, IN_C);

    cudaStreamWaitEvent(0, s_join, 0);   // join CSR + W2 split before aggregation

    // ---- Layer 1 aggregate ----
    k_agg<6, 0, true><<<(N_NODES * 32 + T - 1) / T, T>>>(h, b1, batch, out_node);

    // ---- Layer 2 GEMM: h2pre = h1 @ W2 (A pre-split by agg1 epilogue) ----
    k_gemm<false><<<dim3(OUT_C / 128, (N_NODES + 127) / 128), 256, 2 * STAGE_B>>>(
        nullptr, (const __nv_bfloat16*)p_Ah, (const __nv_bfloat16*)p_Al,
        (const __nv_bfloat16*)p_B2h, (const __nv_bfloat16*)p_B2l,
        h, N_NODES, OUT_C, HID);

    // ---- Layer 2 aggregate ----
    k_agg<5, 64, false><<<(N_NODES * 32 + T - 1) / T, T>>>(h, b2, batch, out_node);

    // ---- Pool means ----
    k_pooldiv<<<(N_GRAPHS * F4_TOT + T - 1) / T, T>>>(out_graph);
}

// round 17
// speedup vs baseline: 1.0142x; 1.0142x over previous
#include <cuda_runtime.h>
#include <cuda_bf16.h>
#include <cstdint>

// Problem constants (fixed by the dataset)
#define N_NODES  50000
#define N_EDGES  800000
#define IN_C     768
#define HID      256
#define OUT_C    128
#define N_GRAPHS 256
#define F_TOT    384
#define F4_TOT   96

// ---------------------------------------------------------------------------
// Scratch (device globals)
// ---------------------------------------------------------------------------
__device__ float g_h   [N_NODES * HID];     // GEMM output (pre-agg), reused both layers
__device__ float g_deg [N_NODES];
__device__ float g_dinv[N_NODES];
__device__ float g_pool[N_GRAPHS * F_TOT];
__device__ float g_cnt [N_GRAPHS];
__device__ int   g_idx64;

// CSR
__device__ int   g_off   [N_NODES + 1];
__device__ int   g_cursor[N_NODES];
__device__ int   g_csr   [N_EDGES];
__device__ float g_csrw  [N_EDGES];

// bf16 split A for layer-2 GEMM (filled by agg1 epilogue)
__device__ __nv_bfloat16 g_Ah[N_NODES * HID];
__device__ __nv_bfloat16 g_Al[N_NODES * HID];
// bf16 split weights [N][K]
__device__ __nv_bfloat16 g_B1h[HID * IN_C];
__device__ __nv_bfloat16 g_B1l[HID * IN_C];
__device__ __nv_bfloat16 g_B2h[OUT_C * HID];
__device__ __nv_bfloat16 g_B2l[OUT_C * HID];

// ---------------------------------------------------------------------------
// Helpers
// ---------------------------------------------------------------------------
__device__ __forceinline__ uint32_t smem_to_u32(const void* p) {
    uint32_t a;
    asm("{ .reg .u64 t; cvta.to.shared.u64 t, %1; cvt.u32.u64 %0, t; }"
        : "=r"(a) : "l"(p));
    return a;
}
__device__ __forceinline__ void ldsm_x4(uint32_t* r, uint32_t addr) {
    asm volatile("ldmatrix.sync.aligned.m8n8.x4.shared.b16 {%0,%1,%2,%3}, [%4];"
                 : "=r"(r[0]), "=r"(r[1]), "=r"(r[2]), "=r"(r[3]) : "r"(addr));
}
__device__ __forceinline__ void ldsm_x2(uint32_t* r, uint32_t addr) {
    asm volatile("ldmatrix.sync.aligned.m8n8.x2.shared.b16 {%0,%1}, [%2];"
                 : "=r"(r[0]), "=r"(r[1]) : "r"(addr));
}
__device__ __forceinline__ void mma_bf16(float* d, const uint32_t* a, const uint32_t* b) {
    asm volatile("mma.sync.aligned.m16n8k16.row.col.f32.bf16.bf16.f32 "
                 "{%0,%1,%2,%3}, {%4,%5,%6,%7}, {%8,%9}, {%0,%1,%2,%3};"
                 : "+f"(d[0]), "+f"(d[1]), "+f"(d[2]), "+f"(d[3])
                 : "r"(a[0]), "r"(a[1]), "r"(a[2]), "r"(a[3]),
                   "r"(b[0]), "r"(b[1]));
}
__device__ __forceinline__ void cp16(uint32_t dst, const void* src, int bytes) {
    asm volatile("cp.async.ca.shared.global [%0], [%1], 16, %2;"
                 :: "r"(dst), "l"(src), "r"(bytes) : "memory");
}
#define CP_COMMIT() asm volatile("cp.async.commit_group;" ::: "memory")
template <int NG> __device__ __forceinline__ void cp_wait() {
    asm volatile("cp.async.wait_group %0;" :: "n"(NG) : "memory");
}

// Scalar bf16 split
__device__ __forceinline__ void bf16_split(float x, unsigned short& hi, unsigned short& lo) {
    __nv_bfloat16 h = __float2bfloat16(x);
    float r = x - __bfloat162float(h);
    __nv_bfloat16 l = __float2bfloat16(r);
    hi = __bfloat16_as_ushort(h);
    lo = __bfloat16_as_ushort(l);
}

// Packed float4 -> (hi bf16x4, lo bf16x4) split via cvt.rn.bf16x2.f32.
__device__ __forceinline__ void split_f4(float4 v, uint2& hw, uint2& lw) {
    uint32_t h01, h23;
    asm("cvt.rn.bf16x2.f32 %0, %1, %2;" : "=r"(h01) : "f"(v.y), "f"(v.x));
    asm("cvt.rn.bf16x2.f32 %0, %1, %2;" : "=r"(h23) : "f"(v.w), "f"(v.z));
    float r0 = v.x - __uint_as_float(h01 << 16);
    float r1 = v.y - __uint_as_float(h01 & 0xFFFF0000u);
    float r2 = v.z - __uint_as_float(h23 << 16);
    float r3 = v.w - __uint_as_float(h23 & 0xFFFF0000u);
    uint32_t l01, l23;
    asm("cvt.rn.bf16x2.f32 %0, %1, %2;" : "=r"(l01) : "f"(r1), "f"(r0));
    asm("cvt.rn.bf16x2.f32 %0, %1, %2;" : "=r"(l23) : "f"(r3), "f"(r2));
    hw = make_uint2(h01, h23);
    lw = make_uint2(l01, l23);
}

__device__ __forceinline__ int load_idx(const void* p, long long i) {
    if (g_idx64) return (int)((const long long*)p)[i];
    return ((const int*)p)[i];
}
__device__ __forceinline__ void red_add_v4(float* p, float x, float y, float z, float w) {
    asm volatile("red.global.add.v4.f32 [%0], {%1,%2,%3,%4};"
                 :: "l"(p), "f"(x), "f"(y), "f"(z), "f"(w) : "memory");
}

// ---------------------------------------------------------------------------
// Prolog kernels
// ---------------------------------------------------------------------------
__global__ void k_detect(const void* ei) {
    if (threadIdx.x == 0 && blockIdx.x == 0) {
        const long long* p = (const long long*)ei;
        int ok = 1;
        for (int i = 0; i < 256; i++) {
            long long v = p[i];
            if (v < 0 || v >= N_NODES) { ok = 0; break; }
        }
        g_idx64 = ok;
    }
}

__global__ void k_zero() {
    int i = blockIdx.x * blockDim.x + threadIdx.x;
    if (i < N_NODES) g_deg[i] = 0.f;
    if (i < N_GRAPHS * F_TOT) g_pool[i] = 0.f;
    if (i < N_GRAPHS) g_cnt[i] = 0.f;
}

// Combined W1+W2 split (round-9/15 proven placement: main stream, pre-GEMM1)
__global__ void k_splitW(const float* __restrict__ W1, const float* __restrict__ W2) {
    int i = blockIdx.x * blockDim.x + threadIdx.x;
    if (i < IN_C * HID) {
        int k = i / HID, n = i % HID;
        unsigned short hi, lo;
        bf16_split(W1[i], hi, lo);
        g_B1h[n * IN_C + k] = __ushort_as_bfloat16(hi);
        g_B1l[n * IN_C + k] = __ushort_as_bfloat16(lo);
    } else {
        int j = i - IN_C * HID;
        if (j < HID * OUT_C) {
            int k = j / OUT_C, n = j % OUT_C;
            unsigned short hi, lo;
            bf16_split(W2[j], hi, lo);
            g_B2h[n * HID + k] = __ushort_as_bfloat16(hi);
            g_B2l[n * HID + k] = __ushort_as_bfloat16(lo);
        }
    }
}

__global__ void k_deg(const void* __restrict__ ei) {
    int e = blockIdx.x * blockDim.x + threadIdx.x;
    if (e < N_EDGES) {
        int d = load_idx(ei, (long long)N_EDGES + e);
        atomicAdd(&g_deg[d], 1.0f);
    }
}
__global__ void k_dinv() {
    int i = blockIdx.x * blockDim.x + threadIdx.x;
    if (i < N_NODES) g_dinv[i] = rsqrtf(g_deg[i] + 1.0f);
}
__global__ void k_cnt(const void* __restrict__ batch) {
    int i = blockIdx.x * blockDim.x + threadIdx.x;
    if (i < N_NODES) {
        int g = load_idx(batch, i);
        atomicAdd(&g_cnt[g], 1.0f);
    }
}

// Exclusive scan of deg -> g_off / g_cursor. Single block, 1024 threads.
__global__ void k_scan() {
    __shared__ int swarp[32];
    __shared__ int s_carry;
    int tid = threadIdx.x, lane = tid & 31, wid = tid >> 5;
    if (tid == 0) s_carry = 0;
    __syncthreads();
    for (int base = 0; base < N_NODES; base += 1024) {
        int i = base + tid;
        int v = (i < N_NODES) ? (int)g_deg[i] : 0;
        int incl = v;
#pragma unroll
        for (int o = 1; o < 32; o <<= 1) {
            int t = __shfl_up_sync(0xFFFFFFFFu, incl, o);
            if (lane >= o) incl += t;
        }
        if (lane == 31) swarp[wid] = incl;
        __syncthreads();
        if (wid == 0) {
            int ws = swarp[lane];
            int wincl = ws;
#pragma unroll
            for (int o = 1; o < 32; o <<= 1) {
                int t = __shfl_up_sync(0xFFFFFFFFu, wincl, o);
                if (lane >= o) wincl += t;
            }
            swarp[lane] = wincl - ws;
        }
        __syncthreads();
        int ex = s_carry + swarp[wid] + incl - v;
        if (i < N_NODES) { g_off[i] = ex; g_cursor[i] = ex; }
        __syncthreads();
        if (tid == 1023) s_carry = ex + v;
        __syncthreads();
    }
    if (threadIdx.x == 0) g_off[N_NODES] = s_carry;
}

__global__ void k_fill(const void* __restrict__ ei) {
    int e = blockIdx.x * blockDim.x + threadIdx.x;
    if (e >= N_EDGES) return;
    int s = load_idx(ei, e);
    int d = load_idx(ei, (long long)N_EDGES + e);
    int p = atomicAdd(&g_cursor[d], 1);
    g_csr[p]  = s;
    g_csrw[p] = g_dinv[s] * g_dinv[d];
}

// ---------------------------------------------------------------------------
// Pipelined bf16-split GEMM (round-15 proven).
//   AFP32=true : A fp32 [M,K]; double-buffered A32, single Astage, double
//                Bstage (92 KB -> 2 CTAs/SM); prefetch-first pipeline.
//   AFP32=false: A pre-split bf16 hi/lo arrays (double-buffered, 80 KB).
// ---------------------------------------------------------------------------
#define PITCH    80
#define TILE_B   (128 * PITCH)        // 10240
#define STAGE_B  (4 * TILE_B)         // 40960 (AFP32=false stage)
#define A32_B    16384                // 128 x 32 fp32
#define SMEM_T   (2 * A32_B + 2 * TILE_B + 4 * TILE_B)   // 94208 (AFP32=true)

template <bool AFP32>
__global__ void __launch_bounds__(256, 2)
k_gemm(const float* __restrict__ A32,
       const __nv_bfloat16* __restrict__ Ah, const __nv_bfloat16* __restrict__ Al,
       const __nv_bfloat16* __restrict__ Bh, const __nv_bfloat16* __restrict__ Bl,
       float* __restrict__ C, int M, int Nld, int K) {
    extern __shared__ char smem[];
    const int tid  = threadIdx.x;
    const int lane = tid & 31;
    const int wid  = tid >> 5;
    const int wm   = (wid & 1) * 64;
    const int wn   = (wid >> 1) * 32;
    const int mBase = blockIdx.y * 128;
    const int nBase = blockIdx.x * 128;
    const uint32_t sbase = smem_to_u32(smem);
    const uint32_t sAstage = sbase + 2 * A32_B;
    const uint32_t sBstage = sAstage + 2 * TILE_B;

    float acc[4][4][4];
#pragma unroll
    for (int i = 0; i < 4; i++)
#pragma unroll
        for (int j = 0; j < 4; j++)
#pragma unroll
            for (int q = 0; q < 4; q++) acc[i][j][q] = 0.f;

    const int aRow = lane & 15;
    const int aK   = (lane >> 4) * 16;
    const int bRow = lane & 7;
    const int bK   = ((lane & 15) >> 3) * 16;

    const int nch = K >> 5;

    auto stage = [&](int ch, int buf) {
        const int k0 = ch << 5;
        if (AFP32) {
            const uint32_t sa = sbase + buf * A32_B;
#pragma unroll
            for (int t = 0; t < 4; t++) {
                int idx = t * 256 + tid;          // 0..1023
                int m = idx >> 3, q = idx & 7;
                int gm = mBase + m;
                int ok = (gm < M) ? 16 : 0;
                if (!ok) gm = 0;
                cp16(sa + m * 128 + q * 16, A32 + (size_t)gm * K + k0 + q * 4, ok);
            }
            const uint32_t sbB = sBstage + buf * (2 * TILE_B);
#pragma unroll
            for (int t = 0; t < 2; t++) {
                int idx = t * 256 + tid;          // 0..511
                int n = idx >> 2, q = idx & 3;
                uint32_t so = sbB + n * PITCH + q * 16;
                const size_t gb = (size_t)(nBase + n) * K + k0 + q * 8;
                cp16(so,          Bh + gb, 16);
                cp16(so + TILE_B, Bl + gb, 16);
            }
        } else {
            const uint32_t sb = sbase + buf * STAGE_B;
#pragma unroll
            for (int t = 0; t < 2; t++) {
                int idx = t * 256 + tid;          // 0..511
                int m = idx >> 2, q = idx & 3;
                uint32_t so = sb + m * PITCH + q * 16;
                int gm = mBase + m;
                int okA = (gm < M) ? 16 : 0;
                if (!okA) gm = 0;
                const size_t ga = (size_t)gm * K + k0 + q * 8;
                cp16(so,              Ah + ga, okA);
                cp16(so + TILE_B,     Al + ga, okA);
                const size_t gb = (size_t)(nBase + m) * K + k0 + q * 8;
                cp16(so + 2 * TILE_B, Bh + gb, 16);
                cp16(so + 3 * TILE_B, Bl + gb, 16);
            }
        }
    };

    stage(0, 0); CP_COMMIT();
    for (int ch = 0; ch < nch; ch++) {
        const int buf = ch & 1;

        if (ch + 1 < nch) { stage(ch + 1, buf ^ 1); CP_COMMIT(); cp_wait<1>(); }
        else              { cp_wait<0>(); }
        __syncthreads();

        if (AFP32) {
            // split A32[buf] -> Astage (single-buffered; protected by loop-end sync)
#pragma unroll
            for (int t = 0; t < 4; t++) {
                int idx = t * 256 + tid;          // 0..1023 float4s
                int m = idx >> 3, q = idx & 7;
                float4 v = *(const float4*)(smem + buf * A32_B + m * 128 + q * 16);
                uint2 hw, lw;
                split_f4(v, hw, lw);
                char* so = smem + 2 * A32_B + m * PITCH + q * 8;
                *(uint2*)(so)          = hw;
                *(uint2*)(so + TILE_B) = lw;
            }
            __syncthreads();
        }

        const uint32_t aBase = AFP32 ? sAstage : (sbase + buf * STAGE_B);
        const uint32_t bBase = AFP32 ? (sBstage + buf * (2 * TILE_B))
                                     : (aBase + 2 * TILE_B);

#pragma unroll
        for (int ks = 0; ks < 2; ks++) {
            const int koff = ks * 32;
            uint32_t bhf[4][2], blf[4][2];
#pragma unroll
            for (int nf = 0; nf < 4; nf++) {
                uint32_t ro = bBase + (uint32_t)(wn + nf * 8 + bRow) * PITCH + koff + bK;
                ldsm_x2(bhf[nf], ro);
                ldsm_x2(blf[nf], ro + TILE_B);
            }
#pragma unroll
            for (int mf = 0; mf < 4; mf++) {
                uint32_t ah[4], al[4];
                uint32_t ro = aBase + (uint32_t)(wm + mf * 16 + aRow) * PITCH + koff + aK;
                ldsm_x4(ah, ro);
                ldsm_x4(al, ro + TILE_B);
#pragma unroll
                for (int nf = 0; nf < 4; nf++) {
                    mma_bf16(acc[mf][nf], ah, bhf[nf]);
                    mma_bf16(acc[mf][nf], ah, blf[nf]);
                    mma_bf16(acc[mf][nf], al, bhf[nf]);
                }
            }
        }
        __syncthreads();
    }

#pragma unroll
    for (int mf = 0; mf < 4; mf++) {
        int r0 = mBase + wm + mf * 16 + (lane >> 2);
#pragma unroll
        for (int nf = 0; nf < 4; nf++) {
            int c0 = nBase + wn + nf * 8 + (lane & 3) * 2;
            if (r0 < M)
                *(float2*)(C + (size_t)r0 * Nld + c0) =
                    make_float2(acc[mf][nf][0], acc[mf][nf][1]);
            if (r0 + 8 < M)
                *(float2*)(C + (size_t)(r0 + 8) * Nld + c0) =
                    make_float2(acc[mf][nf][2], acc[mf][nf][3]);
        }
    }
}

// ---------------------------------------------------------------------------
// Fused CSR aggregation (warp per node): selfloop + gather + relu + bias +
// node_embed + pool red + optional bf16 split for next GEMM.
// ---------------------------------------------------------------------------
template <int SH, int COFF, bool SPLIT_OUT>
__global__ void __launch_bounds__(256)
k_agg(const float* __restrict__ h, const float* __restrict__ bias,
      const void* __restrict__ batch, float* __restrict__ out_node) {
    const int gw   = (blockIdx.x * blockDim.x + threadIdx.x) >> 5;
    const int lane = threadIdx.x & 31;
    if (gw >= N_NODES) return;
    const int i = gw;
    constexpr int C = 1 << (SH - 5);
    const float4* h4 = (const float4*)h;

    float4 acc[C];
    const float di = g_dinv[i];
    const float s2 = di * di;
#pragma unroll
    for (int c = 0; c < C; c++) {
        float4 v = h4[((size_t)i << SH) + lane + c * 32];
        acc[c] = make_float4(v.x * s2, v.y * s2, v.z * s2, v.w * s2);
    }

    int j  = g_off[i];
    const int je = g_off[i + 1];
    for (; j + 1 < je; j += 2) {
        int   s0 = g_csr[j],     s1 = g_csr[j + 1];
        float w0 = g_csrw[j],    w1 = g_csrw[j + 1];
        float4 v0[C], v1[C];
#pragma unroll
        for (int c = 0; c < C; c++) {
            v0[c] = h4[((size_t)s0 << SH) + lane + c * 32];
            v1[c] = h4[((size_t)s1 << SH) + lane + c * 32];
        }
#pragma unroll
        for (int c = 0; c < C; c++) {
            acc[c].x += v0[c].x * w0 + v1[c].x * w1;
            acc[c].y += v0[c].y * w0 + v1[c].y * w1;
            acc[c].z += v0[c].z * w0 + v1[c].z * w1;
            acc[c].w += v0[c].w * w0 + v1[c].w * w1;
        }
    }
    if (j < je) {
        int   s0 = g_csr[j];
        float w0 = g_csrw[j];
#pragma unroll
        for (int c = 0; c < C; c++) {
            float4 v = h4[((size_t)s0 << SH) + lane + c * 32];
            acc[c].x += v.x * w0; acc[c].y += v.y * w0;
            acc[c].z += v.z * w0; acc[c].w += v.w * w0;
        }
    }

    const int g = load_idx(batch, i);
    const float4* bias4 = (const float4*)bias;
#pragma unroll
    for (int c = 0; c < C; c++) {
        float4 bb = bias4[lane + c * 32];
        float4 a;
        a.x = fmaxf(acc[c].x + bb.x, 0.f);
        a.y = fmaxf(acc[c].y + bb.y, 0.f);
        a.z = fmaxf(acc[c].z + bb.z, 0.f);
        a.w = fmaxf(acc[c].w + bb.w, 0.f);
        ((float4*)out_node)[(size_t)i * F4_TOT + COFF + lane + c * 32] = a;
        red_add_v4(g_pool + (((size_t)g * F4_TOT + COFF + lane + c * 32) << 2),
                   a.x, a.y, a.z, a.w);
        if (SPLIT_OUT) {
            uint2 hw, lw;
            split_f4(a, hw, lw);
            size_t o = ((size_t)i << SH) + lane + c * 32;
            ((uint2*)g_Ah)[o] = hw;
            ((uint2*)g_Al)[o] = lw;
        }
    }
}

__global__ void k_pooldiv(float* __restrict__ out_graph) {
    int tid = blockIdx.x * blockDim.x + threadIdx.x;
    if (tid >= N_GRAPHS * F4_TOT) return;
    int g = tid / F4_TOT;
    float inv = 1.0f / fmaxf(g_cnt[g], 1.0f);
    float4 v = ((float4*)g_pool)[tid];
    v.x *= inv; v.y *= inv; v.z *= inv; v.w *= inv;
    ((float4*)out_graph)[tid] = v;
}

// ---------------------------------------------------------------------------
// Launch -- EXACT round-15 schedule (best measured, 367.3 us): k_zero on
// main, CSR chain on side overlapping GEMM1, combined splitW on main,
// everything else strictly serial. All alternative schedules measured worse.
// ---------------------------------------------------------------------------
extern "C" void kernel_launch(void* const* d_in, const int* in_sizes, int n_in,
                              void* d_out, int out_size) {
    const float* x     = (const float*)d_in[0];
    const void*  ei    = d_in[1];
    const void*  batch = d_in[2];
    const float *W1, *b1, *W2, *b2;
    if (n_in >= 8) {
        W1 = (const float*)d_in[4]; b1 = (const float*)d_in[5];
        W2 = (const float*)d_in[6]; b2 = (const float*)d_in[7];
    } else {
        W1 = (const float*)d_in[3]; b1 = (const float*)d_in[4];
        W2 = (const float*)d_in[5]; b2 = (const float*)d_in[6];
    }
    float* out       = (float*)d_out;
    float* out_graph = out;
    float* out_node  = out + (size_t)N_GRAPHS * F_TOT;

    void *p_h, *p_Ah, *p_Al, *p_B1h, *p_B1l, *p_B2h, *p_B2l;
    cudaGetSymbolAddress(&p_h,   g_h);
    cudaGetSymbolAddress(&p_Ah,  g_Ah);
    cudaGetSymbolAddress(&p_Al,  g_Al);
    cudaGetSymbolAddress(&p_B1h, g_B1h);
    cudaGetSymbolAddress(&p_B1l, g_B1l);
    cudaGetSymbolAddress(&p_B2h, g_B2h);
    cudaGetSymbolAddress(&p_B2l, g_B2l);
    float* h = (float*)p_h;

    cudaFuncSetAttribute(k_gemm<true>,  cudaFuncAttributeMaxDynamicSharedMemorySize,
                         SMEM_T);
    cudaFuncSetAttribute(k_gemm<false>, cudaFuncAttributeMaxDynamicSharedMemorySize,
                         2 * STAGE_B);

    // Side stream + events (created once; first call is the non-captured
    // correctness run, so creation never happens inside capture).
    static cudaStream_t s_side = nullptr;
    static cudaEvent_t  s_fork = nullptr, s_join = nullptr;
    if (!s_side) {
        cudaStreamCreateWithFlags(&s_side, cudaStreamNonBlocking);
        cudaEventCreateWithFlags(&s_fork, cudaEventDisableTiming);
        cudaEventCreateWithFlags(&s_join, cudaEventDisableTiming);
    }

    const int T = 256;
    k_zero<<<(N_GRAPHS * F_TOT + T - 1) / T, T>>>();

    // ---- fork: CSR build on side stream, GEMM1 on main ----
    cudaEventRecord(s_fork, 0);
    cudaStreamWaitEvent(s_side, s_fork, 0);
    k_detect<<<1, 32, 0, s_side>>>(ei);
    k_deg<<<(N_EDGES + T - 1) / T, T, 0, s_side>>>(ei);
    k_dinv<<<(N_NODES + T - 1) / T, T, 0, s_side>>>();
    k_cnt<<<(N_NODES + T - 1) / T, T, 0, s_side>>>(batch);
    k_scan<<<1, 1024, 0, s_side>>>();
    k_fill<<<(N_EDGES + T - 1) / T, T, 0, s_side>>>(ei);
    cudaEventRecord(s_join, s_side);

    k_splitW<<<(IN_C * HID + HID * OUT_C + T - 1) / T, T>>>(W1, W2);
    // Layer 1 GEMM: h = x @ W1 (A split fused, fp32 input)
    k_gemm<true><<<dim3(HID / 128, (N_NODES + 127) / 128), 256, SMEM_T>>>(
        x, nullptr, nullptr,
        (const __nv_bfloat16*)p_B1h, (const __nv_bfloat16*)p_B1l,
        h, N_NODES, HID, IN_C);

    cudaStreamWaitEvent(0, s_join, 0);   // join CSR before aggregation

    // ---- Layer 1 aggregate ----
    k_agg<6, 0, true><<<(N_NODES * 32 + T - 1) / T, T>>>(h, b1, batch, out_node);

    // ---- Layer 2 GEMM: h2pre = h1 @ W2 (A pre-split by agg1 epilogue) ----
    k_gemm<false><<<dim3(OUT_C / 128, (N_NODES + 127) / 128), 256, 2 * STAGE_B>>>(
        nullptr, (const __nv_bfloat16*)p_Ah, (const __nv_bfloat16*)p_Al,
        (const __nv_bfloat16*)p_B2h, (const __nv_bfloat16*)p_B2l,
        h, N_NODES, OUT_C, HID);

    // ---- Layer 2 aggregate ----
    k_agg<5, 64, false><<<(N_NODES * 32 + T - 1) / T, T>>>(h, b2, batch, out_node);

    // ---- Pool means ----
    k_pooldiv<<<(N_GRAPHS * F4_TOT + T - 1) / T, T>>>(out_graph);
}